// round 1
// baseline (speedup 1.0000x reference)
#include <cuda_runtime.h>

// Problem constants
#define DD   11      // embedding dim (C+1)
#define NTOK 49      // real (non-zero) tokens per pixel: 7x7 window
#define SEQ  900     // 30*30 canvas
#define FFD  64      // feedforward dim
#define NPIX 256     // 16*16 pixels
#define SCALE 0.30151134457776363f  // 1/sqrt(11)

__global__ __launch_bounds__(256, 4)
void pve_kernel(const float* __restrict__ x,      // [10,16,16]
                const float* __restrict__ Wqkv,   // [33,11]
                const float* __restrict__ Wo,     // [11,11]
                const float* __restrict__ W1,     // [64,11]
                const float* __restrict__ W2,     // [11,64]
                const float* __restrict__ ln1,    // [11]
                const float* __restrict__ ln2,    // [11]
                float* __restrict__ out)          // [256,10,900]
{
    __shared__ float sTok[NTOK][DD];      // gathered window tokens
    __shared__ float sK[NTOK][DD];
    __shared__ float sV[NTOK][DD];
    __shared__ float sRes[NTOK + 1][DD];  // per-token final output; [49] = zero-token result
    __shared__ float sWqkv[3 * DD * DD];
    __shared__ float sWo[DD * DD];
    __shared__ float sW1[FFD * DD];
    __shared__ float sW2[DD * FFD];
    __shared__ float sLn1[DD], sLn2[DD];

    const int tid = threadIdx.x;
    const int b   = blockIdx.x;       // pixel index = h*16 + w
    const int h   = b >> 4;
    const int w   = b & 15;

    // ---- cooperative loads: weights -> shared ----
    for (int i = tid; i < 3 * DD * DD; i += blockDim.x) sWqkv[i] = Wqkv[i];
    for (int i = tid; i < DD * DD;     i += blockDim.x) sWo[i]   = Wo[i];
    for (int i = tid; i < FFD * DD;    i += blockDim.x) sW1[i]   = W1[i];
    for (int i = tid; i < DD * FFD;    i += blockDim.x) sW2[i]   = W2[i];
    if (tid < DD) { sLn1[tid] = ln1[tid]; sLn2[tid] = ln2[tid]; }

    // ---- gather the 49 window tokens (padded x + mask channel) ----
    for (int i = tid; i < NTOK * DD; i += blockDim.x) {
        int k = i / DD, c = i - k * DD;
        int wi = k / 7, wj = k - wi * 7;
        int hh = h + wi - 3, ww = w + wj - 3;
        bool inb = ((unsigned)hh < 16u) && ((unsigned)ww < 16u);
        float v;
        if (c < 10) v = inb ? x[c * 256 + hh * 16 + ww] : 0.0f;
        else        v = inb ? 0.0f : 1.0f;               // mask channel
        sTok[k][c] = v;
    }
    __syncthreads();

    // ---- per-token transformer pipeline; threads 0..48 real tokens, 49 = zero token ----
    const bool active = (tid <= NTOK);
    float xt[DD], q[DD];

    if (active) {
        #pragma unroll
        for (int d = 0; d < DD; d++) xt[d] = (tid < NTOK) ? sTok[tid][d] : 0.0f;

        // qkv = xt @ Wqkv.T  (rows 0..10 -> q, 11..21 -> k, 22..32 -> v)
        #pragma unroll
        for (int o = 0; o < DD; o++) {
            float aq = 0.f, ak = 0.f, av = 0.f;
            #pragma unroll
            for (int d = 0; d < DD; d++) {
                float xv = xt[d];
                aq = fmaf(xv, sWqkv[o * DD + d],            aq);
                ak = fmaf(xv, sWqkv[(o + DD) * DD + d],     ak);
                av = fmaf(xv, sWqkv[(o + 2 * DD) * DD + d], av);
            }
            q[o] = aq;
            if (tid < NTOK) { sK[tid][o] = ak; sV[tid][o] = av; }
        }
    }
    __syncthreads();

    if (active) {
        // ---- attention over 49 real keys; 851 zero keys add exp(-m) each to denom ----
        float lg[NTOK];
        float m = 0.0f;  // max over logits, including the 851 zero logits
        #pragma unroll 7
        for (int j = 0; j < NTOK; j++) {
            float a = 0.f;
            #pragma unroll
            for (int d = 0; d < DD; d++) a = fmaf(q[d], sK[j][d], a);
            a *= SCALE;
            lg[j] = a;
            m = fmaxf(m, a);
        }
        float denom = 851.0f * __expf(-m);
        float sa[DD];
        #pragma unroll
        for (int d = 0; d < DD; d++) sa[d] = 0.f;
        #pragma unroll 7
        for (int j = 0; j < NTOK; j++) {
            float e = __expf(lg[j] - m);
            denom += e;
            #pragma unroll
            for (int d = 0; d < DD; d++) sa[d] = fmaf(e, sV[j][d], sa[d]);
        }
        float inv = 1.0f / denom;

        // ---- out proj + residual ----
        float hd[DD];
        #pragma unroll
        for (int o = 0; o < DD; o++) {
            float a = 0.f;
            #pragma unroll
            for (int e = 0; e < DD; e++) a = fmaf(sa[e], sWo[o * DD + e], a);
            hd[o] = xt[o] + a * inv;
        }

        // ---- LayerNorm 1 ----
        {
            float mean = 0.f;
            #pragma unroll
            for (int d = 0; d < DD; d++) mean += hd[d];
            mean *= (1.0f / DD);
            float var = 0.f;
            #pragma unroll
            for (int d = 0; d < DD; d++) { float t = hd[d] - mean; var = fmaf(t, t, var); }
            var *= (1.0f / DD);
            float rstd = rsqrtf(var + 1e-5f);
            #pragma unroll
            for (int d = 0; d < DD; d++) hd[d] = (hd[d] - mean) * rstd * sLn1[d];
        }

        // ---- FFN: relu(hd @ W1.T) @ W2.T, accumulated on the fly ----
        float y[DD];
        #pragma unroll
        for (int d = 0; d < DD; d++) y[d] = 0.f;
        #pragma unroll 8
        for (int f = 0; f < FFD; f++) {
            float a = 0.f;
            #pragma unroll
            for (int d = 0; d < DD; d++) a = fmaf(hd[d], sW1[f * DD + d], a);
            a = fmaxf(a, 0.0f);
            #pragma unroll
            for (int d = 0; d < DD; d++) y[d] = fmaf(a, sW2[d * FFD + f], y[d]);
        }
        #pragma unroll
        for (int d = 0; d < DD; d++) y[d] += hd[d];

        // ---- LayerNorm 2 -> result ----
        {
            float mean = 0.f;
            #pragma unroll
            for (int d = 0; d < DD; d++) mean += y[d];
            mean *= (1.0f / DD);
            float var = 0.f;
            #pragma unroll
            for (int d = 0; d < DD; d++) { float t = y[d] - mean; var = fmaf(t, t, var); }
            var *= (1.0f / DD);
            float rstd = rsqrtf(var + 1e-5f);
            #pragma unroll
            for (int d = 0; d < DD; d++) sRes[tid][d] = (y[d] - mean) * rstd * sLn2[d];
        }
    }
    __syncthreads();

    // ---- coalesced output write: out[b, c, s]; non-window s -> zero-token result ----
    const long long base = (long long)b * (10 * SEQ);
    for (int i = tid; i < 10 * SEQ; i += blockDim.x) {
        int c = i / SEQ, s = i - c * SEQ;
        int r = s / 30, cc = s - r * 30;
        int tok = (r < 7 && cc < 7) ? (r * 7 + cc) : NTOK;
        out[base + i] = sRes[tok][c];
    }
}

extern "C" void kernel_launch(void* const* d_in, const int* in_sizes, int n_in,
                              void* d_out, int out_size)
{
    const float* x    = (const float*)d_in[0];
    const float* Wqkv = (const float*)d_in[1];
    const float* Wo   = (const float*)d_in[2];
    const float* W1   = (const float*)d_in[3];
    const float* W2   = (const float*)d_in[4];
    const float* ln1  = (const float*)d_in[5];
    const float* ln2  = (const float*)d_in[6];
    float* out = (float*)d_out;

    pve_kernel<<<NPIX, 256>>>(x, Wqkv, Wo, W1, W2, ln1, ln2, out);
}

// round 2
// speedup vs baseline: 1.0950x; 1.0950x over previous
#include <cuda_runtime.h>

// Problem constants
#define DD   11      // embedding dim (C+1)
#define NTOK 49      // real (non-zero) tokens per pixel: 7x7 window
#define SEQ  900     // 30*30 canvas
#define FFD  64      // feedforward dim
#define NPIX 256     // 16*16 pixels
#define SCALE 0.30151134457776363f  // 1/sqrt(11)

__global__ __launch_bounds__(256, 4)
void pve_kernel(const float* __restrict__ x,      // [10,16,16]
                const float* __restrict__ Wqkv,   // [33,11]
                const float* __restrict__ Wo,     // [11,11]
                const float* __restrict__ W1,     // [64,11]
                const float* __restrict__ W2,     // [11,64]
                const float* __restrict__ ln1,    // [11]
                const float* __restrict__ ln2,    // [11]
                float* __restrict__ out)          // [256,10,900]
{
    __shared__ float sTok[NTOK][DD];      // gathered window tokens
    __shared__ float sK[NTOK][DD];
    __shared__ float sV[NTOK][DD];
    __shared__ float sRes[NTOK + 1][DD];  // per-token final output; [49] = zero-token result
    __shared__ float sWqkv[3 * DD * DD];
    __shared__ float sWo[DD * DD];
    __shared__ float sW1[FFD * DD];
    __shared__ float sW2[DD * FFD];
    __shared__ float sLn1[DD], sLn2[DD];

    const int tid = threadIdx.x;
    const int b   = blockIdx.x;       // pixel index = h*16 + w
    const int h   = b >> 4;
    const int w   = b & 15;

    // ---- cooperative loads: weights -> shared ----
    for (int i = tid; i < 3 * DD * DD; i += blockDim.x) sWqkv[i] = Wqkv[i];
    for (int i = tid; i < DD * DD;     i += blockDim.x) sWo[i]   = Wo[i];
    for (int i = tid; i < FFD * DD;    i += blockDim.x) sW1[i]   = W1[i];
    for (int i = tid; i < DD * FFD;    i += blockDim.x) sW2[i]   = W2[i];
    if (tid < DD) { sLn1[tid] = ln1[tid]; sLn2[tid] = ln2[tid]; }

    // ---- gather the 49 window tokens (padded x + mask channel) ----
    for (int i = tid; i < NTOK * DD; i += blockDim.x) {
        int k = i / DD, c = i - k * DD;
        int wi = k / 7, wj = k - wi * 7;
        int hh = h + wi - 3, ww = w + wj - 3;
        bool inb = ((unsigned)hh < 16u) && ((unsigned)ww < 16u);
        float v;
        if (c < 10) v = inb ? x[c * 256 + hh * 16 + ww] : 0.0f;
        else        v = inb ? 0.0f : 1.0f;               // mask channel
        sTok[k][c] = v;
    }
    __syncthreads();

    // ---- qkv for the 49 real tokens (threads 0..48) ----
    float xt[DD], q[DD];
    if (tid < NTOK) {
        #pragma unroll
        for (int d = 0; d < DD; d++) xt[d] = sTok[tid][d];

        // qkv = xt @ Wqkv.T  (rows 0..10 -> q, 11..21 -> k, 22..32 -> v)
        #pragma unroll
        for (int o = 0; o < DD; o++) {
            float aq = 0.f, ak = 0.f, av = 0.f;
            #pragma unroll
            for (int d = 0; d < DD; d++) {
                float xv = xt[d];
                aq = fmaf(xv, sWqkv[o * DD + d],            aq);
                ak = fmaf(xv, sWqkv[(o + DD) * DD + d],     ak);
                av = fmaf(xv, sWqkv[(o + 2 * DD) * DD + d], av);
            }
            q[o] = aq;
            sK[tid][o] = ak;
            sV[tid][o] = av;
        }
    }
    __syncthreads();   // sK, sV visible to everyone

    // =====================================================================
    // Warps 0-1 (threads 0..48): full attention pipeline per real token.
    // Thread 64 (warp 2): zero-token pipeline (q=0 -> uniform attention).
    // Warps 2-7 (threads 64..255): after zero-token result, blanket-fill
    // the whole output with the zero-token value (float4 splat), fully
    // overlapped with warps 0-1's compute. Window positions patched later.
    // =====================================================================

    if (tid < NTOK) {
        // ---- attention over 49 real keys; 851 zero keys add exp(-m) each to denom ----
        float lg[NTOK];
        float m = 0.0f;  // max over logits, including the 851 zero logits
        #pragma unroll 7
        for (int j = 0; j < NTOK; j++) {
            float a = 0.f;
            #pragma unroll
            for (int d = 0; d < DD; d++) a = fmaf(q[d], sK[j][d], a);
            a *= SCALE;
            lg[j] = a;
            m = fmaxf(m, a);
        }
        float denom = 851.0f * __expf(-m);
        float sa[DD];
        #pragma unroll
        for (int d = 0; d < DD; d++) sa[d] = 0.f;
        #pragma unroll 7
        for (int j = 0; j < NTOK; j++) {
            float e = __expf(lg[j] - m);
            denom += e;
            #pragma unroll
            for (int d = 0; d < DD; d++) sa[d] = fmaf(e, sV[j][d], sa[d]);
        }
        float inv = 1.0f / denom;

        // ---- out proj + residual ----
        float hd[DD];
        #pragma unroll
        for (int o = 0; o < DD; o++) {
            float a = 0.f;
            #pragma unroll
            for (int e = 0; e < DD; e++) a = fmaf(sa[e], sWo[o * DD + e], a);
            hd[o] = xt[o] + a * inv;
        }

        // ---- LayerNorm 1 ----
        {
            float mean = 0.f;
            #pragma unroll
            for (int d = 0; d < DD; d++) mean += hd[d];
            mean *= (1.0f / DD);
            float var = 0.f;
            #pragma unroll
            for (int d = 0; d < DD; d++) { float t = hd[d] - mean; var = fmaf(t, t, var); }
            var *= (1.0f / DD);
            float rstd = rsqrtf(var + 1e-5f);
            #pragma unroll
            for (int d = 0; d < DD; d++) hd[d] = (hd[d] - mean) * rstd * sLn1[d];
        }

        // ---- FFN: relu(hd @ W1.T) @ W2.T ----
        float y[DD];
        #pragma unroll
        for (int d = 0; d < DD; d++) y[d] = 0.f;
        #pragma unroll 8
        for (int f = 0; f < FFD; f++) {
            float a = 0.f;
            #pragma unroll
            for (int d = 0; d < DD; d++) a = fmaf(hd[d], sW1[f * DD + d], a);
            a = fmaxf(a, 0.0f);
            #pragma unroll
            for (int d = 0; d < DD; d++) y[d] = fmaf(a, sW2[d * FFD + f], y[d]);
        }
        #pragma unroll
        for (int d = 0; d < DD; d++) y[d] += hd[d];

        // ---- LayerNorm 2 -> result ----
        {
            float mean = 0.f;
            #pragma unroll
            for (int d = 0; d < DD; d++) mean += y[d];
            mean *= (1.0f / DD);
            float var = 0.f;
            #pragma unroll
            for (int d = 0; d < DD; d++) { float t = y[d] - mean; var = fmaf(t, t, var); }
            var *= (1.0f / DD);
            float rstd = rsqrtf(var + 1e-5f);
            #pragma unroll
            for (int d = 0; d < DD; d++) sRes[tid][d] = (y[d] - mean) * rstd * sLn2[d];
        }
    }
    else if (tid == 64) {
        // ---- zero-token pipeline: xt=0, q=k=v=0 ----
        // logits all 0 (real and zero keys) -> uniform softmax 1/900
        // sa = sum(real V) / 900
        float sa[DD];
        #pragma unroll
        for (int d = 0; d < DD; d++) sa[d] = 0.f;
        for (int j = 0; j < NTOK; j++) {
            #pragma unroll
            for (int d = 0; d < DD; d++) sa[d] += sV[j][d];
        }
        const float inv = 1.0f / 900.0f;

        float hd[DD];
        #pragma unroll
        for (int o = 0; o < DD; o++) {
            float a = 0.f;
            #pragma unroll
            for (int e = 0; e < DD; e++) a = fmaf(sa[e], sWo[o * DD + e], a);
            hd[o] = a * inv;   // residual xt = 0
        }
        // LN1
        {
            float mean = 0.f;
            #pragma unroll
            for (int d = 0; d < DD; d++) mean += hd[d];
            mean *= (1.0f / DD);
            float var = 0.f;
            #pragma unroll
            for (int d = 0; d < DD; d++) { float t = hd[d] - mean; var = fmaf(t, t, var); }
            var *= (1.0f / DD);
            float rstd = rsqrtf(var + 1e-5f);
            #pragma unroll
            for (int d = 0; d < DD; d++) hd[d] = (hd[d] - mean) * rstd * sLn1[d];
        }
        // FFN
        float y[DD];
        #pragma unroll
        for (int d = 0; d < DD; d++) y[d] = 0.f;
        #pragma unroll 8
        for (int f = 0; f < FFD; f++) {
            float a = 0.f;
            #pragma unroll
            for (int d = 0; d < DD; d++) a = fmaf(hd[d], sW1[f * DD + d], a);
            a = fmaxf(a, 0.0f);
            #pragma unroll
            for (int d = 0; d < DD; d++) y[d] = fmaf(a, sW2[d * FFD + f], y[d]);
        }
        #pragma unroll
        for (int d = 0; d < DD; d++) y[d] += hd[d];
        // LN2
        {
            float mean = 0.f;
            #pragma unroll
            for (int d = 0; d < DD; d++) mean += y[d];
            mean *= (1.0f / DD);
            float var = 0.f;
            #pragma unroll
            for (int d = 0; d < DD; d++) { float t = y[d] - mean; var = fmaf(t, t, var); }
            var *= (1.0f / DD);
            float rstd = rsqrtf(var + 1e-5f);
            #pragma unroll
            for (int d = 0; d < DD; d++) sRes[NTOK][d] = (y[d] - mean) * rstd * sLn2[d];
        }
    }

    // ---- warps 2-7: wait for zero-token result, then blanket-fill output ----
    if (tid >= 64) {
        asm volatile("bar.sync 1, 192;" ::: "memory");   // warps 2-7 only; fences shared
        // out4 index i in [0, 2250): i = c*225 + q  (q = float4 index within c-plane)
        float4* out4 = reinterpret_cast<float4*>(out + (long long)b * (10 * SEQ));
        for (int i = tid - 64; i < 10 * (SEQ / 4); i += 192) {
            int c = i / 225;
            float zc = sRes[NTOK][c];
            out4[i] = make_float4(zc, zc, zc, zc);
        }
    }
    __syncthreads();   // real-token results ready; blanket stores fenced before patch

    // ---- patch the 490 window elements: out[b, c, r*30+cc] = sRes[r*7+cc][c] ----
    float* ob = out + (long long)b * (10 * SEQ);
    for (int i = tid; i < NTOK * 10; i += blockDim.x) {
        int tok = i / 10, c = i - tok * 10;
        int r = tok / 7, cc = tok - r * 7;
        ob[c * SEQ + r * 30 + cc] = sRes[tok][c];
    }
}

extern "C" void kernel_launch(void* const* d_in, const int* in_sizes, int n_in,
                              void* d_out, int out_size)
{
    const float* x    = (const float*)d_in[0];
    const float* Wqkv = (const float*)d_in[1];
    const float* Wo   = (const float*)d_in[2];
    const float* W1   = (const float*)d_in[3];
    const float* W2   = (const float*)d_in[4];
    const float* ln1  = (const float*)d_in[5];
    const float* ln2  = (const float*)d_in[6];
    float* out = (float*)d_out;

    pve_kernel<<<NPIX, 256>>>(x, Wqkv, Wo, W1, W2, ln1, ln2, out);
}